// round 3
// baseline (speedup 1.0000x reference)
#include <cuda_runtime.h>
#include <math.h>
#include <stdint.h>

// ---------------------------------------------------------------------------
// GDER: out[b] = mean( Rx^2 + Ry^2 ) over valid 498x498 map.
// sum(Gy) is cancellation noise (~1e-17) => Gy/sum(Gy) taps ~1e15 and Ry^2
// dominates everything else by >1e16 relative. Only the Gy path is computed,
// as a separable conv Gy = A(y)*B(x), 1/sum(Gy) folded into vertical taps.
// sum(Gy) replicated on host in numpy's exact f64 pairwise order
// (validated R1/R2: rel_err 8.7e-8).
//
// R3: software-pipelined row loads (LDG latency off the critical chain),
// single barrier per row (double buffer), TILE_ROWS=15 (2176 blocks, static
// ring indices), reduced register pressure.
// ---------------------------------------------------------------------------

#define NB        64
#define W         512
#define OUTW      498
#define TILE_ROWS 15
#define TILES_Y   34      // 34*15 = 510 >= 498

typedef unsigned long long u64;

struct Weights {
    float hw[8];   // horizontal symmetric taps: hw[0..6] pair weights, hw[7] center
    float vw[7];   // vertical antisymmetric taps (scaled by 1/sum(Gy))
};

__device__ double g_partials[NB * TILES_Y];
__device__ int    g_count[NB];   // zero-initialized; self-resetting

// ---- f32x2 packed helpers (sm_100+) ----
__device__ __forceinline__ u64 pack2(float lo, float hi) {
    u64 r; asm("mov.b64 %0, {%1, %2};" : "=l"(r) : "f"(lo), "f"(hi)); return r;
}
__device__ __forceinline__ void unpack2(u64 v, float& lo, float& hi) {
    asm("mov.b64 {%0, %1}, %2;" : "=f"(lo), "=f"(hi) : "l"(v));
}
__device__ __forceinline__ u64 fma2(u64 a, u64 b, u64 c) {
    u64 d; asm("fma.rn.f32x2 %0, %1, %2, %3;" : "=l"(d) : "l"(a), "l"(b), "l"(c)); return d;
}
__device__ __forceinline__ u64 add2(u64 a, u64 b) {
    u64 d; asm("add.rn.f32x2 %0, %1, %2;" : "=l"(d) : "l"(a), "l"(b)); return d;
}
__device__ __forceinline__ u64 mul2(u64 a, u64 b) {
    u64 d; asm("mul.rn.f32x2 %0, %1, %2;" : "=l"(d) : "l"(a), "l"(b)); return d;
}
__device__ __forceinline__ u64 neg2(u64 a) {        // flip both sign bits (ALU pipe)
    return a ^ 0x8000000080000000ull;
}

__global__ __launch_bounds__(128, 4) void gder_kernel(const float* __restrict__ x,
                                                      Weights wt,
                                                      float* __restrict__ out)
{
    const int t     = threadIdx.x;
    const int tileY = blockIdx.x;
    const int b     = blockIdx.y;
    const int y0    = tileY * TILE_ROWS;
    const float* __restrict__ img = x + (size_t)b * W * W;

    // vertical results, packed (v[i], v[i+256]); entries 256..269 written each
    // row by t<7 as (v[256+i], 0) for right-edge window wrap
    __shared__ __align__(16) u64 vbuf[2][272];
    __shared__ double red[128];

    // packed weights: horizontal 8, vertical 7 (no negated copies — saves regs)
    u64 hw2[8], vp[7];
    #pragma unroll
    for (int j = 0; j < 8; ++j) hw2[j] = pack2(wt.hw[j], wt.hw[j]);
    #pragma unroll
    for (int k = 0; k < 7; ++k) vp[k] = pack2(wt.vw[k], wt.vw[k]);

    const int c = 2 * t;   // packed stream indices c, c+1; lanes = (col, col+256)

    // register ring: 15 rows x 2 packed streams
    u64 h0[15], h1[15];
    #pragma unroll
    for (int i = 0; i < 14; ++i) {
        const float2 L = *reinterpret_cast<const float2*>(img + (size_t)(y0 + i) * W + c);
        const float2 R = *reinterpret_cast<const float2*>(img + (size_t)(y0 + i) * W + c + 256);
        h0[i] = pack2(L.x, R.x);
        h1[i] = pack2(L.y, R.y);
    }

    // prefetch first compute row (y0+14 <= 509 < 512 always valid)
    float2 pfL = *reinterpret_cast<const float2*>(img + (size_t)(y0 + 14) * W + c);
    float2 pfR = *reinterpret_cast<const float2*>(img + (size_t)(y0 + 14) * W + c + 256);

    u64 facc = 0ull;
    int buf = 0;

    #pragma unroll
    for (int p = 0; p < TILE_ROWS; ++p) {
        // consume prefetched row into ring slot (constant index per unrolled p)
        h0[(14 + p) % 15] = pack2(pfL.x, pfR.x);
        h1[(14 + p) % 15] = pack2(pfL.y, pfR.y);

        // issue prefetch for next row (hidden behind this row's compute)
        {
            const int gr = y0 + 15 + p;
            if (gr < W) {
                pfL = *reinterpret_cast<const float2*>(img + (size_t)gr * W + c);
                pfR = *reinterpret_cast<const float2*>(img + (size_t)gr * W + c + 256);
            } else {
                pfL = make_float2(0.f, 0.f);
                pfR = make_float2(0.f, 0.f);
            }
        }

        // vertical (antisymmetric): s = sum_k vw[k]*row_k  -  sum_k vw[k]*row_{14-k}
        u64 a0 = 0ull, b0 = 0ull, a1 = 0ull, b1 = 0ull;
        #pragma unroll
        for (int k = 0; k < 7; ++k) {
            a0 = fma2(vp[k], h0[(p + k) % 15], a0);
            b0 = fma2(vp[k], h0[(p + 14 - k) % 15], b0);
            a1 = fma2(vp[k], h1[(p + k) % 15], a1);
            b1 = fma2(vp[k], h1[(p + 14 - k) % 15], b1);
        }
        const u64 s0 = add2(a0, neg2(b0));
        const u64 s1 = add2(a1, neg2(b1));

        *reinterpret_cast<ulonglong2*>(&vbuf[buf][c]) = make_ulonglong2(s0, s1);
        if (t < 7) {   // right-edge extension: (hi lane value, 0)
            float lo0, hi0, lo1, hi1;
            unpack2(s0, lo0, hi0);
            unpack2(s1, lo1, hi1);
            vbuf[buf][256 + c]     = pack2(hi0, 0.f);
            vbuf[buf][256 + c + 1] = pack2(hi1, 0.f);
        }
        __syncthreads();   // single barrier/row: double buffer covers WAR hazard

        // horizontal (symmetric), packed, 2 outputs per thread
        if (y0 + p < OUTW) {
            u64 win[16];
            #pragma unroll
            for (int q = 0; q < 8; ++q) {
                const ulonglong2 v2 =
                    *reinterpret_cast<const ulonglong2*>(&vbuf[buf][c + 2 * q]);
                win[2 * q]     = v2.x;
                win[2 * q + 1] = v2.y;
            }
            #pragma unroll
            for (int k = 0; k < 2; ++k) {
                u64 o = mul2(hw2[7], win[k + 7]);
                #pragma unroll
                for (int j = 0; j < 7; ++j)
                    o = fma2(hw2[j], add2(win[k + j], win[k + 14 - j]), o);
                // hi lane = output col 256+c+k; invalid beyond 497 (t > 120)
                if (t > 120) o &= 0x00000000FFFFFFFFull;
                facc = fma2(o, o, facc);
            }
        }
        buf ^= 1;
    }

    // deterministic block reduction in double
    {
        float flo, fhi;
        unpack2(facc, flo, fhi);
        red[t] = (double)flo + (double)fhi;
    }
    __syncthreads();
    #pragma unroll
    for (int s = 64; s > 0; s >>= 1) {
        if (t < s) red[t] += red[t + s];
        __syncthreads();
    }
    if (t == 0) {
        g_partials[b * TILES_Y + tileY] = red[0];
        __threadfence();
        const int old = atomicAdd(&g_count[b], 1);
        if (old == TILES_Y - 1) {   // last block for this batch: fixed-order final sum
            __threadfence();
            double s = 0.0;
            #pragma unroll
            for (int i = 0; i < TILES_Y; ++i)
                s += __ldcg(&g_partials[b * TILES_Y + i]);
            out[b] = (float)(s * (1.0 / ((double)OUTW * (double)OUTW)));
            g_count[b] = 0;         // reset for next graph replay
        }
    }
}

// ---------------------------------------------------------------------------
// Host side: replicate numpy float64 semantics exactly (validated in R1/R2).
// ---------------------------------------------------------------------------

// numpy's pairwise_sum for contiguous float64 (PW_BLOCKSIZE = 128)
static double np_pairwise(const double* a, int n)
{
    if (n < 8) {
        double res = 0.0;
        for (int i = 0; i < n; ++i) res += a[i];
        return res;
    }
    else if (n <= 128) {
        double r[8];
        for (int j = 0; j < 8; ++j) r[j] = a[j];
        int i;
        for (i = 8; i < n - (n % 8); i += 8)
            for (int j = 0; j < 8; ++j) r[j] += a[i + j];
        double res = ((r[0] + r[1]) + (r[2] + r[3])) + ((r[4] + r[5]) + (r[6] + r[7]));
        for (; i < n; ++i) res += a[i];
        return res;
    }
    else {
        int n2 = n / 2;
        n2 -= n2 % 8;
        return np_pairwise(a, n2) + np_pairwise(a + n2, n - n2);
    }
}

extern "C" void kernel_launch(void* const* d_in, const int* in_sizes, int n_in,
                              void* d_out, int out_size)
{
    (void)in_sizes; (void)n_in; (void)out_size;
    const float* x  = (const float*)d_in[0];
    float*      out = (float*)d_out;

    const double sig     = 7.0 / 2.5;              // N=15//2=7; sig = N/2.5
    const double sig2    = pow(sig, 2.0);          // sig ** 2 (CPython float_pow -> libm pow)
    const double twosig2 = 2.0 * sig2;
    const double denomG  = (2.0 * M_PI) * sig;

    double Gy[225];
    for (int i = 0; i < 15; ++i) {
        const int yy = i - 7;
        for (int j = 0; j < 15; ++j) {
            const int xx = j - 7;
            const double G = exp((double)(-(xx * xx + yy * yy)) / twosig2) / denomG;
            Gy[i * 15 + j] = ((double)(-yy) * G) / sig2;
        }
    }
    const double s = np_pairwise(Gy, 225);         // np.sum(Gy), numpy pairwise order

    Weights wt;
    for (int j = 0; j < 8; ++j) {
        const int xx = j - 7;
        wt.hw[j] = (float)(exp((double)(-(xx * xx)) / twosig2) / denomG);
    }
    for (int k = 0; k < 7; ++k) {
        const int yy = k - 7;
        const double A = (((double)(-yy) * exp((double)(-(yy * yy)) / twosig2)) / sig2) / s;
        wt.vw[k] = (float)A;
    }

    dim3 grid(TILES_Y, NB);
    gder_kernel<<<grid, 128>>>(x, wt, out);
}

// round 4
// speedup vs baseline: 1.0624x; 1.0624x over previous
#include <cuda_runtime.h>
#include <math.h>
#include <stdint.h>

// ---------------------------------------------------------------------------
// GDER: out[b] = mean( Rx^2 + Ry^2 ) over valid 498x498 map.
// sum(Gy) is cancellation noise (~1e-17) => Gy/sum(Gy) taps ~1e15 and Ry^2
// dominates everything else by >1e16 relative. Only the Gy path is computed,
// as a separable conv Gy = A(y)*B(x), 1/sum(Gy) folded into vertical taps.
// sum(Gy) replicated on host in numpy's exact f64 pairwise order
// (validated R1-R3: rel_err ~8.7e-8).
//
// R4: TILE_ROWS=30 (R2 amortization) + R3's prefetch/single-barrier,
// branch-free clamped prefetch, fma(-1,b,a) combine (no ALU xor), hoisted
// row-base pointers (constant LDG offsets).
// ---------------------------------------------------------------------------

#define NB        64
#define W         512
#define OUTW      498
#define TILE_ROWS 30
#define TILES_Y   17      // 17*30 = 510 >= 498

typedef unsigned long long u64;

struct Weights {
    float hw[8];   // horizontal symmetric taps: hw[0..6] pair weights, hw[7] center
    float vw[7];   // vertical antisymmetric taps (scaled by 1/sum(Gy))
};

__device__ double g_partials[NB * TILES_Y];
__device__ int    g_count[NB];   // zero-initialized; self-resetting

// ---- f32x2 packed helpers (sm_100+) ----
__device__ __forceinline__ u64 pack2(float lo, float hi) {
    u64 r; asm("mov.b64 %0, {%1, %2};" : "=l"(r) : "f"(lo), "f"(hi)); return r;
}
__device__ __forceinline__ void unpack2(u64 v, float& lo, float& hi) {
    asm("mov.b64 {%0, %1}, %2;" : "=f"(lo), "=f"(hi) : "l"(v));
}
__device__ __forceinline__ u64 fma2(u64 a, u64 b, u64 c) {
    u64 d; asm("fma.rn.f32x2 %0, %1, %2, %3;" : "=l"(d) : "l"(a), "l"(b), "l"(c)); return d;
}
__device__ __forceinline__ u64 add2(u64 a, u64 b) {
    u64 d; asm("add.rn.f32x2 %0, %1, %2;" : "=l"(d) : "l"(a), "l"(b)); return d;
}
__device__ __forceinline__ u64 mul2(u64 a, u64 b) {
    u64 d; asm("mul.rn.f32x2 %0, %1, %2;" : "=l"(d) : "l"(a), "l"(b)); return d;
}

__global__ __launch_bounds__(128) void gder_kernel(const float* __restrict__ x,
                                                   Weights wt,
                                                   float* __restrict__ out)
{
    const int t     = threadIdx.x;
    const int tileY = blockIdx.x;
    const int b     = blockIdx.y;
    const int y0    = tileY * TILE_ROWS;
    const float* __restrict__ img = x + (size_t)b * W * W;

    // vertical results, packed (v[i], v[i+256]); entries 256..269 written each
    // row by t<7 as (v[256+i], 0) for right-edge window wrap
    __shared__ __align__(16) u64 vbuf[2][272];
    __shared__ double red[128];

    // packed weights
    u64 hw2[8], vp[7];
    #pragma unroll
    for (int j = 0; j < 8; ++j) hw2[j] = pack2(wt.hw[j], wt.hw[j]);
    #pragma unroll
    for (int k = 0; k < 7; ++k) vp[k] = pack2(wt.vw[k], wt.vw[k]);
    const u64 negone = pack2(-1.f, -1.f);

    const int c = 2 * t;   // packed stream indices c, c+1; lanes = (col, col+256)

    // hoisted row-base pointers: loads below use constant row offsets
    const float* __restrict__ pL = img + c;
    const float* __restrict__ pR = img + c + 256;

    // register ring: 15 rows x 2 packed streams
    u64 h0[15], h1[15];
    #pragma unroll
    for (int i = 0; i < 14; ++i) {
        const float2 L = *reinterpret_cast<const float2*>(pL + (size_t)(y0 + i) * W);
        const float2 R = *reinterpret_cast<const float2*>(pR + (size_t)(y0 + i) * W);
        h0[i] = pack2(L.x, R.x);
        h1[i] = pack2(L.y, R.y);
    }

    // prefetch first compute row (y0+14 <= 509 always valid)
    float2 pfL = *reinterpret_cast<const float2*>(pL + (size_t)(y0 + 14) * W);
    float2 pfR = *reinterpret_cast<const float2*>(pR + (size_t)(y0 + 14) * W);

    u64 facc = 0ull;
    int buf = 0;

    for (int g = 0; g < 2; ++g) {
        #pragma unroll
        for (int p = 0; p < 15; ++p) {
            const int r = 15 * g + p;          // row index within tile

            // consume prefetched row into ring slot (constant index per p)
            h0[(14 + p) % 15] = pack2(pfL.x, pfR.x);
            h1[(14 + p) % 15] = pack2(pfL.y, pfR.y);

            // branch-free prefetch of next row: clamp to last row. Rows past
            // 511 are consumed only by outputs >= 498, which are discarded,
            // so the clamped (wrong) data never reaches facc.
            {
                int gr = y0 + 15 + r;
                gr = gr < (W - 1) ? gr : (W - 1);
                pfL = *reinterpret_cast<const float2*>(pL + (size_t)gr * W);
                pfR = *reinterpret_cast<const float2*>(pR + (size_t)gr * W);
            }

            // vertical (antisymmetric): s = A - B, A = sum vw[k]*row_k,
            // B = sum vw[k]*row_{14-k}; combine via fma(-1, B, A) (fma pipe)
            u64 a0 = 0ull, b0 = 0ull, a1 = 0ull, b1 = 0ull;
            #pragma unroll
            for (int k = 0; k < 7; ++k) {
                a0 = fma2(vp[k], h0[(p + k) % 15], a0);
                b0 = fma2(vp[k], h0[(p + 14 - k) % 15], b0);
                a1 = fma2(vp[k], h1[(p + k) % 15], a1);
                b1 = fma2(vp[k], h1[(p + 14 - k) % 15], b1);
            }
            const u64 s0 = fma2(negone, b0, a0);
            const u64 s1 = fma2(negone, b1, a1);

            *reinterpret_cast<ulonglong2*>(&vbuf[buf][c]) = make_ulonglong2(s0, s1);
            if (t < 7) {   // right-edge extension: (hi lane value, 0)
                float lo0, hi0, lo1, hi1;
                unpack2(s0, lo0, hi0);
                unpack2(s1, lo1, hi1);
                vbuf[buf][256 + c]     = pack2(hi0, 0.f);
                vbuf[buf][256 + c + 1] = pack2(hi1, 0.f);
            }
            __syncthreads();   // single barrier/row: double buffer covers WAR

            // horizontal (symmetric), packed, 2 packed outputs per thread
            if (y0 + r < OUTW) {
                u64 win[16];
                #pragma unroll
                for (int q = 0; q < 8; ++q) {
                    const ulonglong2 v2 =
                        *reinterpret_cast<const ulonglong2*>(&vbuf[buf][c + 2 * q]);
                    win[2 * q]     = v2.x;
                    win[2 * q + 1] = v2.y;
                }
                #pragma unroll
                for (int k = 0; k < 2; ++k) {
                    u64 o = mul2(hw2[7], win[k + 7]);
                    #pragma unroll
                    for (int j = 0; j < 7; ++j)
                        o = fma2(hw2[j], add2(win[k + j], win[k + 14 - j]), o);
                    // hi lane = output col 256+c+k; invalid beyond 497 (t > 120)
                    if (t > 120) o &= 0x00000000FFFFFFFFull;
                    facc = fma2(o, o, facc);
                }
            }
            buf ^= 1;
        }
    }

    // deterministic block reduction in double
    {
        float flo, fhi;
        unpack2(facc, flo, fhi);
        red[t] = (double)flo + (double)fhi;
    }
    __syncthreads();
    #pragma unroll
    for (int s = 64; s > 0; s >>= 1) {
        if (t < s) red[t] += red[t + s];
        __syncthreads();
    }
    if (t == 0) {
        g_partials[b * TILES_Y + tileY] = red[0];
        __threadfence();
        const int old = atomicAdd(&g_count[b], 1);
        if (old == TILES_Y - 1) {   // last block for this batch: fixed-order final sum
            __threadfence();
            double s = 0.0;
            #pragma unroll
            for (int i = 0; i < TILES_Y; ++i)
                s += __ldcg(&g_partials[b * TILES_Y + i]);
            out[b] = (float)(s * (1.0 / ((double)OUTW * (double)OUTW)));
            g_count[b] = 0;         // reset for next graph replay
        }
    }
}

// ---------------------------------------------------------------------------
// Host side: replicate numpy float64 semantics exactly (validated R1-R3).
// ---------------------------------------------------------------------------

// numpy's pairwise_sum for contiguous float64 (PW_BLOCKSIZE = 128)
static double np_pairwise(const double* a, int n)
{
    if (n < 8) {
        double res = 0.0;
        for (int i = 0; i < n; ++i) res += a[i];
        return res;
    }
    else if (n <= 128) {
        double r[8];
        for (int j = 0; j < 8; ++j) r[j] = a[j];
        int i;
        for (i = 8; i < n - (n % 8); i += 8)
            for (int j = 0; j < 8; ++j) r[j] += a[i + j];
        double res = ((r[0] + r[1]) + (r[2] + r[3])) + ((r[4] + r[5]) + (r[6] + r[7]));
        for (; i < n; ++i) res += a[i];
        return res;
    }
    else {
        int n2 = n / 2;
        n2 -= n2 % 8;
        return np_pairwise(a, n2) + np_pairwise(a + n2, n - n2);
    }
}

extern "C" void kernel_launch(void* const* d_in, const int* in_sizes, int n_in,
                              void* d_out, int out_size)
{
    (void)in_sizes; (void)n_in; (void)out_size;
    const float* x  = (const float*)d_in[0];
    float*      out = (float*)d_out;

    const double sig     = 7.0 / 2.5;              // N=15//2=7; sig = N/2.5
    const double sig2    = pow(sig, 2.0);          // sig ** 2 (CPython float_pow -> libm pow)
    const double twosig2 = 2.0 * sig2;
    const double denomG  = (2.0 * M_PI) * sig;

    double Gy[225];
    for (int i = 0; i < 15; ++i) {
        const int yy = i - 7;
        for (int j = 0; j < 15; ++j) {
            const int xx = j - 7;
            const double G = exp((double)(-(xx * xx + yy * yy)) / twosig2) / denomG;
            Gy[i * 15 + j] = ((double)(-yy) * G) / sig2;
        }
    }
    const double s = np_pairwise(Gy, 225);         // np.sum(Gy), numpy pairwise order

    Weights wt;
    for (int j = 0; j < 8; ++j) {
        const int xx = j - 7;
        wt.hw[j] = (float)(exp((double)(-(xx * xx)) / twosig2) / denomG);
    }
    for (int k = 0; k < 7; ++k) {
        const int yy = k - 7;
        const double A = (((double)(-yy) * exp((double)(-(yy * yy)) / twosig2)) / sig2) / s;
        wt.vw[k] = (float)A;
    }

    dim3 grid(TILES_Y, NB);
    gder_kernel<<<grid, 128>>>(x, wt, out);
}